// round 5
// baseline (speedup 1.0000x reference)
#include <cuda_runtime.h>
#include <cstdint>
#include <cstddef>

#define T_TOK 8192
#define NJ    24
#define NH    8
#define FD    32
#define JD    6144
#define OUTJ  768

__device__ float g_Q[(size_t)T_TOK * JD];   // [t][h][n][f]
__device__ float g_K[(size_t)T_TOK * JD];
__device__ float g_V[(size_t)T_TOK * JD];
__device__ float g_Wt[(size_t)NJ * OUTJ * 256];   // [n][j][d], tf32-rounded
__device__ float g_bias[NJ * OUTJ];

__device__ __forceinline__ uint32_t smem_u32(const void* p) {
    uint32_t a;
    asm("{ .reg .u64 t; cvta.to.shared.u64 t, %1; cvt.u32.u64 %0, t; }" : "=r"(a) : "l"(p));
    return a;
}
__device__ __forceinline__ unsigned f2tf32(float x) {
    unsigned u;
    asm("cvt.rna.tf32.f32 %0, %1;" : "=r"(u) : "f"(x));
    return u;
}
__device__ __forceinline__ void mma_tf32(float* d, const unsigned* a, unsigned b0, unsigned b1) {
    asm volatile(
        "mma.sync.aligned.m16n8k8.row.col.f32.tf32.tf32.f32 "
        "{%0,%1,%2,%3}, {%4,%5,%6,%7}, {%8,%9}, {%0,%1,%2,%3};\n"
        : "+f"(d[0]), "+f"(d[1]), "+f"(d[2]), "+f"(d[3])
        : "r"(a[0]), "r"(a[1]), "r"(a[2]), "r"(a[3]), "r"(b0), "r"(b1));
}
__device__ __forceinline__ void cp16(uint32_t d, const void* s) {
    asm volatile("cp.async.cg.shared.global [%0], [%1], 16;" :: "r"(d), "l"(s));
}
#define CPC()  asm volatile("cp.async.commit_group;" ::: "memory")
#define CPW(n) asm volatile("cp.async.wait_group %0;" :: "n"(n) : "memory")

// ------------------------------- prep ---------------------------------------
__global__ void prep_w_kernel(const float* __restrict__ Wq, const float* __restrict__ Wk,
                              const float* __restrict__ Wv) {
    const size_t total = (size_t)NJ * OUTJ * 256;
    for (size_t i = (size_t)blockIdx.x * blockDim.x + threadIdx.x; i < total;
         i += (size_t)gridDim.x * blockDim.x) {
        int d = (int)(i & 255);
        size_t nj = i >> 8;
        int j = (int)(nj % OUTJ), n = (int)(nj / OUTJ);
        int h = (j >> 5) & 7, f = j & 31;
        float v;
        if (j < 256)      v = Wq[(((size_t)h * NJ + n) * 256 + d) * FD + f];
        else if (j < 512) v = Wk[((size_t)h * 256 + d) * FD + f];
        else              v = Wv[((size_t)h * 256 + d) * FD + f];
        g_Wt[i] = __uint_as_float(f2tf32(v));
    }
}
__global__ void prep_b_kernel(const float* __restrict__ bq, const float* __restrict__ bk,
                              const float* __restrict__ bv) {
    int i = blockIdx.x * blockDim.x + threadIdx.x;
    if (i < NJ * OUTJ) {
        int n = i / OUTJ, j = i % OUTJ, h = (j >> 5) & 7, f = j & 31;
        float v;
        if (j < 256)      v = bq[(h * NJ + n) * FD + f];
        else if (j < 512) v = bk[h * FD + f];
        else              v = bv[h * FD + f];
        g_bias[i] = v;
    }
}

// ------------------ K1: tf32 mma QKV GEMM, 512 thr, fragment-major B --------
// 144 CTAs = 24 joints x 6 col-blocks(128). Per CTA: C[8192x128]=A[8192x256]B^T
// 16 warps as 4(m) x 4(n); warp tile 64x32. 3-stage cp.async A pipeline.
// B permuted once into fragment-major: [kb8][wn4][nt4][half2][lane32]x4floats.
#define OFF_B    0          // 128KB
#define OFF_A    131072     // 3 x 32KB
#define OFF_BIAS 229376
#define SMEM1    229888

__global__ void __launch_bounds__(512, 1)
qkv_gemm3_kernel(const float* __restrict__ x) {
    extern __shared__ char sm[];
    const uint32_t sb = smem_u32(sm);
    float* bias_s = (float*)(sm + OFF_BIAS);
    const int tid = threadIdx.x, warp = tid >> 5, lane = tid & 31;
    const int g = lane >> 2, tg = lane & 3;
    const int wm = warp >> 2, wn = warp & 3;
    const int nj = blockIdx.x / 6, jb = blockIdx.x % 6;

    // prologue: A chunk0 + chunk1 via cp.async (2 groups)
    {
        const float* xb = x + (size_t)nj * 256;
#pragma unroll
        for (int it = 0; it < 4; ++it) {
            int i = tid + 512 * it;            // 2048 16B-chunks
            int row = i >> 3, c4 = i & 7;
            cp16(sb + OFF_A + (uint32_t)(row * 128 + ((c4 ^ (row & 7)) << 4)),
                 xb + (size_t)row * JD + c4 * 4);
        }
        CPC();
        const float* xb1 = xb + 32;
#pragma unroll
        for (int it = 0; it < 4; ++it) {
            int i = tid + 512 * it;
            int row = i >> 3, c4 = i & 7;
            cp16(sb + OFF_A + 32768u + (uint32_t)(row * 128 + ((c4 ^ (row & 7)) << 4)),
                 xb1 + (size_t)row * JD + c4 * 4);
        }
        CPC();
    }
    // B panel: fragment-major permute (one-time, LDG scattered -> STS)
    {
        const float* W = g_Wt + (size_t)(nj * OUTJ + jb * 128) * 256;
        float* Bp = (float*)(sm + OFF_B);
#pragma unroll 4
        for (int fi = tid; fi < 32768; fi += 512) {
            int c  = fi & 3;
            int ln = (fi >> 2) & 31;
            int hf = (fi >> 7) & 1;
            int nt = (fi >> 8) & 3;
            int wc = (fi >> 10) & 3;
            int kb = fi >> 12;
            int kk = 2 * hf + (c >> 1), r = c & 1;
            int n = wc * 32 + nt * 8 + (ln >> 2);
            int k = kb * 32 + kk * 8 + (ln & 3) + r * 4;
            Bp[fi] = W[n * 256 + k];
        }
        if (tid < 128) bias_s[tid] = g_bias[nj * OUTJ + jb * 128 + tid];
    }

    float acc[4][4][4];
#pragma unroll
    for (int mt = 0; mt < 4; ++mt)
#pragma unroll
        for (int nt = 0; nt < 4; ++nt)
#pragma unroll
            for (int r = 0; r < 4; ++r) acc[mt][nt][r] = 0.f;

    uint32_t aRow[4];
#pragma unroll
    for (int mt = 0; mt < 4; ++mt)
        aRow[mt] = (uint32_t)((wm * 64 + mt * 16 + g) * 128 + tg * 4);
    const char* BpW = sm + OFF_B + wn * 4096 + lane * 16;

#pragma unroll 1
    for (int c = 0; c < 256; ++c) {           // chunk = (mtile c>>3, kb c&7)
        CPW(1);
        __syncthreads();
        if (c + 2 < 256) {
            int cn = c + 2;
            const float* xb = x + (size_t)(cn >> 3) * 256 * JD + (size_t)nj * 256 + (cn & 7) * 32;
            uint32_t stb = sb + OFF_A + (uint32_t)(cn % 3) * 32768u;
#pragma unroll
            for (int it = 0; it < 4; ++it) {
                int i = tid + 512 * it;
                int row = i >> 3, c4 = i & 7;
                cp16(stb + (uint32_t)(row * 128 + ((c4 ^ (row & 7)) << 4)),
                     xb + (size_t)row * JD + c4 * 4);
            }
        }
        CPC();

        const char* A0 = sm + OFF_A + (c % 3) * 32768;
        const char* Bk = BpW + (c & 7) * 16384;
#pragma unroll
        for (int kp = 0; kp < 2; ++kp) {
            uint4 bf[4];
#pragma unroll
            for (int nt = 0; nt < 4; ++nt)
                bf[nt] = *(const uint4*)(Bk + nt * 1024 + kp * 512);
#pragma unroll
            for (int q = 0; q < 2; ++q) {
                const int kk = 2 * kp + q;
                const uint32_t x0 = (uint32_t)(((2 * kk) ^ g) << 4);
                const uint32_t x1 = (uint32_t)(((2 * kk + 1) ^ g) << 4);
                unsigned a[4][4];
#pragma unroll
                for (int mt = 0; mt < 4; ++mt) {
                    a[mt][0] = *(const unsigned*)(A0 + aRow[mt] + x0);
                    a[mt][1] = *(const unsigned*)(A0 + aRow[mt] + 1024 + x0);
                    a[mt][2] = *(const unsigned*)(A0 + aRow[mt] + x1);
                    a[mt][3] = *(const unsigned*)(A0 + aRow[mt] + 1024 + x1);
                }
#pragma unroll
                for (int mt = 0; mt < 4; ++mt)
#pragma unroll
                    for (int nt = 0; nt < 4; ++nt)
                        mma_tf32(acc[mt][nt], a[mt],
                                 q ? bf[nt].z : bf[nt].x,
                                 q ? bf[nt].w : bf[nt].y);
            }
        }

        if ((c & 7) == 7) {                    // epilogue for this 256-row m-tile
            const int rbase = (c >> 3) * 256 + wm * 64 + g;
#pragma unroll
            for (int mt = 0; mt < 4; ++mt)
#pragma unroll
                for (int nt = 0; nt < 4; ++nt) {
                    int jl = wn * 32 + nt * 8 + tg * 2;
                    int jg = jb * 128 + jl;
                    float* outp = (jg < 256) ? g_Q : ((jg < 512) ? g_K : g_V);
                    int h = (jg >> 5) & 7, f = jg & 31;
                    float b0 = bias_s[jl], b1 = bias_s[jl + 1];
                    size_t o0 = (size_t)(rbase + mt * 16) * JD + h * OUTJ + nj * 32 + f;
                    *(float2*)&outp[o0] =
                        make_float2(acc[mt][nt][0] + b0, acc[mt][nt][1] + b1);
                    *(float2*)&outp[o0 + 8 * JD] =
                        make_float2(acc[mt][nt][2] + b0, acc[mt][nt][3] + b1);
                    acc[mt][nt][0] = acc[mt][nt][1] = acc[mt][nt][2] = acc[mt][nt][3] = 0.f;
                }
        }
    }
}

// -------- K2: persistent attention + residual + LN, 4 lanes per joint -------
// 148 CTAs x 768 thr (24 warps). warp -> (head = w/3, joint-octet = w%3);
// lane -> (n = lane&7, f-quarter = lane>>3). Double-buffered cp.async k/v.
#define GRID2   148
#define STAGE_F 12288
#define SMEM2   ((2 * STAGE_F + 64) * 4)

__global__ void __launch_bounds__(768, 1)
attn_ln3_kernel(const float* __restrict__ x, const float* __restrict__ gamma,
                const float* __restrict__ beta, float* __restrict__ y) {
    extern __shared__ float sm2[];
    float* red = sm2 + 2 * STAGE_F;
    const uint32_t sb = smem_u32(sm2);
    const int tid = threadIdx.x, warp = tid >> 5, lane = tid & 31;
    const int h = warp >> 2 < 2 ? warp / 3 : warp / 3;   // h = warp/3
    const int wph = warp - h * 3;
    const int n = wph * 8 + (lane & 7);
    const int fb = (lane >> 3) * 8;
    const int t0 = blockIdx.x;

    {   // prologue: stage 0 <- token t0
        const float* Kg = g_K + (size_t)t0 * JD;
        const float* Vg = g_V + (size_t)t0 * JD;
#pragma unroll
        for (int it = 0; it < 2; ++it) {
            int i = tid + 768 * it;            // 1536 16B-chunks each
            cp16(sb + (uint32_t)i * 16, Kg + i * 4);
            cp16(sb + 24576u + (uint32_t)i * 16, Vg + i * 4);
        }
        CPC();
    }
    int it_i = 0;
#pragma unroll 1
    for (int t = t0; t < T_TOK; t += GRID2, ++it_i) {
        const int s = it_i & 1;
        CPW(0);
        __syncthreads();       // k/v staged; previous iter fully done
        const int tn = t + GRID2;
        if (tn < T_TOK) {
            const float* Kg = g_K + (size_t)tn * JD;
            const float* Vg = g_V + (size_t)tn * JD;
            uint32_t db = sb + (uint32_t)(s ^ 1) * (STAGE_F * 4);
#pragma unroll
            for (int it = 0; it < 2; ++it) {
                int i = tid + 768 * it;
                cp16(db + (uint32_t)i * 16, Kg + i * 4);
                cp16(db + 24576u + (uint32_t)i * 16, Vg + i * 4);
            }
        }
        CPC();

        const float* ks = sm2 + s * STAGE_F + h * OUTJ + fb;
        const float* vs = sm2 + s * STAGE_F + 6144 + h * OUTJ + fb;
        const float SC = 0.17677669529663687f;  // 1/sqrt(32)

        float q[8];
        {
            const float* qg = g_Q + (size_t)t * JD + h * OUTJ + n * 32 + fb;
            float4 v0 = *(const float4*)&qg[0];
            float4 v1 = *(const float4*)&qg[4];
            q[0]=v0.x*SC; q[1]=v0.y*SC; q[2]=v0.z*SC; q[3]=v0.w*SC;
            q[4]=v1.x*SC; q[5]=v1.y*SC; q[6]=v1.z*SC; q[7]=v1.w*SC;
        }
        float sc[NJ];
#pragma unroll
        for (int m = 0; m < NJ; ++m) {
            float4 k0 = *(const float4*)&ks[m * 32];
            float4 k1 = *(const float4*)&ks[m * 32 + 4];
            float p = q[0]*k0.x + q[1]*k0.y + q[2]*k0.z + q[3]*k0.w
                    + q[4]*k1.x + q[5]*k1.y + q[6]*k1.z + q[7]*k1.w;
            p += __shfl_xor_sync(0xffffffffu, p, 8);
            p += __shfl_xor_sync(0xffffffffu, p, 16);
            sc[m] = p;
        }
        float mx = sc[0];
#pragma unroll
        for (int m = 1; m < NJ; ++m) mx = fmaxf(mx, sc[m]);
        float sum = 0.f;
#pragma unroll
        for (int m = 0; m < NJ; ++m) { sc[m] = __expf(sc[m] - mx); sum += sc[m]; }
        const float inv = 1.f / sum;

        float yv[8];
        {
            const float* xg = x + (size_t)t * JD + n * 256 + h * 32 + fb;
            float4 v0 = *(const float4*)&xg[0];
            float4 v1 = *(const float4*)&xg[4];
            yv[0]=v0.x; yv[1]=v0.y; yv[2]=v0.z; yv[3]=v0.w;
            yv[4]=v1.x; yv[5]=v1.y; yv[6]=v1.z; yv[7]=v1.w;
        }
#pragma unroll
        for (int m = 0; m < NJ; ++m) {
            float w = sc[m] * inv;
            float4 v0 = *(const float4*)&vs[m * 32];
            float4 v1 = *(const float4*)&vs[m * 32 + 4];
            yv[0] += w*v0.x; yv[1] += w*v0.y; yv[2] += w*v0.z; yv[3] += w*v0.w;
            yv[4] += w*v1.x; yv[5] += w*v1.y; yv[6] += w*v1.z; yv[7] += w*v1.w;
        }
        float s1 = 0.f, s2 = 0.f;
#pragma unroll
        for (int f = 0; f < 8; ++f) { s1 += yv[f]; s2 += yv[f] * yv[f]; }
#pragma unroll
        for (int o = 16; o; o >>= 1) {
            s1 += __shfl_xor_sync(0xffffffffu, s1, o);
            s2 += __shfl_xor_sync(0xffffffffu, s2, o);
        }
        if (lane == 0) { red[warp] = s1; red[32 + warp] = s2; }
        __syncthreads();
        if (warp == 0) {
            float v1 = (lane < 24) ? red[lane] : 0.f;
            float v2 = (lane < 24) ? red[32 + lane] : 0.f;
#pragma unroll
            for (int o = 16; o; o >>= 1) {
                v1 += __shfl_xor_sync(0xffffffffu, v1, o);
                v2 += __shfl_xor_sync(0xffffffffu, v2, o);
            }
            if (lane == 0) {
                float mu = v1 * (1.0f / JD);
                float var = v2 * (1.0f / JD) - mu * mu;
                red[48] = mu;
                red[49] = rsqrtf(var + 1e-5f);
            }
        }
        __syncthreads();
        const float mu = red[48], rstd = red[49];
        {
            const int base = n * 256 + h * 32 + fb;
            float4 g0 = *(const float4*)&gamma[base];
            float4 g1 = *(const float4*)&gamma[base + 4];
            float4 b0 = *(const float4*)&beta[base];
            float4 b1 = *(const float4*)&beta[base + 4];
            float* yt = y + (size_t)t * JD + base;
            float4 o0, o1;
            o0.x = (yv[0]-mu)*rstd*g0.x + b0.x; o0.y = (yv[1]-mu)*rstd*g0.y + b0.y;
            o0.z = (yv[2]-mu)*rstd*g0.z + b0.z; o0.w = (yv[3]-mu)*rstd*g0.w + b0.w;
            o1.x = (yv[4]-mu)*rstd*g1.x + b1.x; o1.y = (yv[5]-mu)*rstd*g1.y + b1.y;
            o1.z = (yv[6]-mu)*rstd*g1.z + b1.z; o1.w = (yv[7]-mu)*rstd*g1.w + b1.w;
            *(float4*)&yt[0] = o0;
            *(float4*)&yt[4] = o1;
        }
    }
}

// ---------------------------------------------------------------------------
extern "C" void kernel_launch(void* const* d_in, const int* in_sizes, int n_in,
                              void* d_out, int out_size) {
    const float* x     = (const float*)d_in[0];
    const float* Wq    = (const float*)d_in[1];
    const float* bq    = (const float*)d_in[2];
    const float* Wk    = (const float*)d_in[3];
    const float* bk    = (const float*)d_in[4];
    const float* Wv    = (const float*)d_in[5];
    const float* bv    = (const float*)d_in[6];
    const float* gamma = (const float*)d_in[7];
    const float* beta  = (const float*)d_in[8];
    float* y = (float*)d_out;

    cudaFuncSetAttribute(qkv_gemm3_kernel, cudaFuncAttributeMaxDynamicSharedMemorySize, SMEM1);
    cudaFuncSetAttribute(attn_ln3_kernel,  cudaFuncAttributeMaxDynamicSharedMemorySize, SMEM2);

    prep_w_kernel<<<4608, 256>>>(Wq, Wk, Wv);
    prep_b_kernel<<<72, 256>>>(bq, bk, bv);
    qkv_gemm3_kernel<<<NJ * 6, 512, SMEM1>>>(x);
    attn_ln3_kernel<<<GRID2, 768, SMEM2>>>(x, gamma, beta, y);
}

// round 6
// speedup vs baseline: 1.3016x; 1.3016x over previous
#include <cuda_runtime.h>
#include <cstdint>
#include <cstddef>

#define T_TOK 8192
#define NJ    24
#define NH    8
#define FD    32
#define JD    6144
#define OUTJ  768

__device__ float g_Q[(size_t)T_TOK * JD];   // [t][h][n][f]
__device__ float g_K[(size_t)T_TOK * JD];
__device__ float g_V[(size_t)T_TOK * JD];
__device__ float g_Wt[(size_t)NJ * OUTJ * 256];   // [n][j][d], tf32-rounded
__device__ float g_bias[NJ * OUTJ];

__device__ __forceinline__ uint32_t smem_u32(const void* p) {
    uint32_t a;
    asm("{ .reg .u64 t; cvta.to.shared.u64 t, %1; cvt.u32.u64 %0, t; }" : "=r"(a) : "l"(p));
    return a;
}
__device__ __forceinline__ unsigned f2tf32(float x) {
    unsigned u;
    asm("cvt.rna.tf32.f32 %0, %1;" : "=r"(u) : "f"(x));
    return u;
}
__device__ __forceinline__ void mma_tf32(float* d, const unsigned* a, const unsigned* b) {
    asm volatile(
        "mma.sync.aligned.m16n8k8.row.col.f32.tf32.tf32.f32 "
        "{%0,%1,%2,%3}, {%4,%5,%6,%7}, {%8,%9}, {%0,%1,%2,%3};\n"
        : "+f"(d[0]), "+f"(d[1]), "+f"(d[2]), "+f"(d[3])
        : "r"(a[0]), "r"(a[1]), "r"(a[2]), "r"(a[3]), "r"(b[0]), "r"(b[1]));
}
__device__ __forceinline__ void cp16(uint32_t d, const void* s) {
    asm volatile("cp.async.cg.shared.global [%0], [%1], 16;" :: "r"(d), "l"(s));
}
#define CPC()  asm volatile("cp.async.commit_group;" ::: "memory")
#define CPW(n) asm volatile("cp.async.wait_group %0;" :: "n"(n) : "memory")

// ------------------------------- prep ---------------------------------------
__global__ void prep_w_kernel(const float* __restrict__ Wq, const float* __restrict__ Wk,
                              const float* __restrict__ Wv) {
    const size_t total = (size_t)NJ * OUTJ * 256;
    for (size_t i = (size_t)blockIdx.x * blockDim.x + threadIdx.x; i < total;
         i += (size_t)gridDim.x * blockDim.x) {
        int d = (int)(i & 255);
        size_t nj = i >> 8;
        int j = (int)(nj % OUTJ), n = (int)(nj / OUTJ);
        int h = (j >> 5) & 7, f = j & 31;
        float v;
        if (j < 256)      v = Wq[(((size_t)h * NJ + n) * 256 + d) * FD + f];
        else if (j < 512) v = Wk[((size_t)h * 256 + d) * FD + f];
        else              v = Wv[((size_t)h * 256 + d) * FD + f];
        g_Wt[i] = __uint_as_float(f2tf32(v));
    }
}
__global__ void prep_b_kernel(const float* __restrict__ bq, const float* __restrict__ bk,
                              const float* __restrict__ bv) {
    int i = blockIdx.x * blockDim.x + threadIdx.x;
    if (i < NJ * OUTJ) {
        int n = i / OUTJ, j = i % OUTJ, h = (j >> 5) & 7, f = j & 31;
        float v;
        if (j < 256)      v = bq[(h * NJ + n) * FD + f];
        else if (j < 512) v = bk[h * FD + f];
        else              v = bv[h * FD + f];
        g_bias[i] = v;
    }
}

// ------------------ K1: tf32 mma QKV GEMM (R4 config) ------------------------
#define OFF_B    0
#define OFF_A    131072
#define OFF_BIAS 229376
#define SMEM1    229888

__global__ void __launch_bounds__(256, 1)
qkv_gemm2_kernel(const float* __restrict__ x) {
    extern __shared__ char sm[];
    const uint32_t sb = smem_u32(sm);
    float* bias_s = (float*)(sm + OFF_BIAS);
    const int tid = threadIdx.x, warp = tid >> 5, lane = tid & 31;
    const int g = lane >> 2, tg = lane & 3;
    const int wm = warp >> 1, wn = warp & 1;
    const int nj = blockIdx.x / 6, jb = blockIdx.x % 6;

    {
        const float* W = g_Wt + (size_t)(nj * OUTJ + jb * 128) * 256;
#pragma unroll
        for (int it = 0; it < 32; ++it) {
            int i = tid + 256 * it;
            int row = i >> 6, c4 = i & 63;
            cp16(sb + OFF_B + (uint32_t)(row * 1024 + ((c4 ^ (row & 7)) << 4)),
                 W + row * 256 + c4 * 4);
        }
        const float* xb = x + (size_t)nj * 256;
#pragma unroll
        for (int it = 0; it < 8; ++it) {
            int i = tid + 256 * it;
            int row = i >> 3, c4 = i & 7;
            cp16(sb + OFF_A + (uint32_t)(row * 128 + ((c4 ^ (row & 7)) << 4)),
                 xb + (size_t)row * JD + c4 * 4);
        }
        if (tid < 128) bias_s[tid] = g_bias[nj * OUTJ + jb * 128 + tid];
        CPC();
        const float* xb1 = xb + 32;
#pragma unroll
        for (int it = 0; it < 8; ++it) {
            int i = tid + 256 * it;
            int row = i >> 3, c4 = i & 7;
            cp16(sb + OFF_A + 32768u + (uint32_t)(row * 128 + ((c4 ^ (row & 7)) << 4)),
                 xb1 + (size_t)row * JD + c4 * 4);
        }
        CPC();
    }

    float acc[4][8][4];
#pragma unroll
    for (int mt = 0; mt < 4; ++mt)
#pragma unroll
        for (int nt = 0; nt < 8; ++nt)
#pragma unroll
            for (int r = 0; r < 4; ++r) acc[mt][nt][r] = 0.f;

    uint32_t aRow[4], bRow[8];
#pragma unroll
    for (int mt = 0; mt < 4; ++mt) aRow[mt] = (uint32_t)((wm * 64 + mt * 16 + g) * 128 + tg * 4);
#pragma unroll
    for (int nt = 0; nt < 8; ++nt) bRow[nt] = (uint32_t)((wn * 64 + nt * 8 + g) * 1024 + tg * 4);

#pragma unroll 1
    for (int c = 0; c < 256; ++c) {
        CPW(1);
        __syncthreads();
        if (c + 2 < 256) {
            int cn = c + 2;
            const float* xb = x + (size_t)(cn >> 3) * 256 * JD + (size_t)nj * 256 + (cn & 7) * 32;
            uint32_t stb = sb + OFF_A + (uint32_t)(cn % 3) * 32768u;
#pragma unroll
            for (int it = 0; it < 8; ++it) {
                int i = tid + 256 * it;
                int row = i >> 3, c4 = i & 7;
                cp16(stb + (uint32_t)(row * 128 + ((c4 ^ (row & 7)) << 4)),
                     xb + (size_t)row * JD + c4 * 4);
            }
        }
        CPC();

        const char* A0 = sm + OFF_A + (c % 3) * 32768;
        const char* B0 = sm + OFF_B + (c & 7) * 128;
#pragma unroll
        for (int kk = 0; kk < 4; ++kk) {
            const uint32_t x0 = (uint32_t)(((2 * kk) ^ g) << 4);
            const uint32_t x1 = (uint32_t)(((2 * kk + 1) ^ g) << 4);
            unsigned a[4][4], b[8][2];
#pragma unroll
            for (int mt = 0; mt < 4; ++mt) {
                a[mt][0] = *(const unsigned*)(A0 + aRow[mt] + x0);
                a[mt][1] = *(const unsigned*)(A0 + aRow[mt] + 1024 + x0);
                a[mt][2] = *(const unsigned*)(A0 + aRow[mt] + x1);
                a[mt][3] = *(const unsigned*)(A0 + aRow[mt] + 1024 + x1);
            }
#pragma unroll
            for (int nt = 0; nt < 8; ++nt) {
                b[nt][0] = *(const unsigned*)(B0 + bRow[nt] + x0);
                b[nt][1] = *(const unsigned*)(B0 + bRow[nt] + x1);
            }
#pragma unroll
            for (int mt = 0; mt < 4; ++mt)
#pragma unroll
                for (int nt = 0; nt < 8; ++nt)
                    mma_tf32(acc[mt][nt], a[mt], b[nt]);
        }

        if ((c & 7) == 7) {
            const int rbase = (c >> 3) * 256 + wm * 64 + g;
#pragma unroll
            for (int mt = 0; mt < 4; ++mt)
#pragma unroll
                for (int nt = 0; nt < 8; ++nt) {
                    int jl = wn * 64 + nt * 8 + tg * 2;
                    int jg = jb * 128 + jl;
                    float* outp = (jg < 256) ? g_Q : ((jg < 512) ? g_K : g_V);
                    int h = (jg >> 5) & 7, f = jg & 31;
                    float b0 = bias_s[jl], b1 = bias_s[jl + 1];
                    size_t o0 = (size_t)(rbase + mt * 16) * JD + h * OUTJ + nj * 32 + f;
                    *(float2*)&outp[o0] =
                        make_float2(acc[mt][nt][0] + b0, acc[mt][nt][1] + b1);
                    *(float2*)&outp[o0 + 8 * JD] =
                        make_float2(acc[mt][nt][2] + b0, acc[mt][nt][3] + b1);
                    acc[mt][nt][0] = acc[mt][nt][1] = acc[mt][nt][2] = acc[mt][nt][3] = 0.f;
                }
        }
    }
}

// -------- K2: column-mapped attention + residual + LN ------------------------
// 148 persistent CTAs x 256 thr. Stage (k|v|q-padded) double-buffered cp.async.
// Phase C: warp=head, lane=joint computes 24 scores + softmax -> smem attn.
// Phase E: thread=(h,f) channel: AV from conflict-free LDS, coalesced x/y/gamma.
#define GRID2   148
#define ST_F    19200                      // floats: k 6144 | v 6144 | q 192*36
#define OFF_ATT (2 * ST_F)                 // 8*24*28 floats
#define OFF_RED (OFF_ATT + 8 * 24 * 28)
#define SMEM2   ((OFF_RED + 64) * 4)       // 175616 B

__global__ void __launch_bounds__(256, 1)
attn_ln4_kernel(const float* __restrict__ x, const float* __restrict__ gamma,
                const float* __restrict__ beta, float* __restrict__ y) {
    extern __shared__ float sm2[];
    float* att = sm2 + OFF_ATT;
    float* red = sm2 + OFF_RED;
    const uint32_t sb = smem_u32(sm2);
    const int tid = threadIdx.x, warp = tid >> 5, lane = tid & 31;
    const int t0 = blockIdx.x;
    const float SC = 0.17677669529663687f;   // 1/sqrt(32)

    // cache gamma/beta columns (channel = tid)
    float gw[NJ], bw[NJ];
#pragma unroll
    for (int n = 0; n < NJ; ++n) { gw[n] = gamma[n * 256 + tid]; bw[n] = beta[n * 256 + tid]; }

    // prologue: stage 0 <- token t0
    {
        const float* Kg = g_K + (size_t)t0 * JD;
        const float* Vg = g_V + (size_t)t0 * JD;
        const float* Qg = g_Q + (size_t)t0 * JD;
#pragma unroll
        for (int it = 0; it < 6; ++it) {
            int i = tid + 256 * it;          // 1536 float4 each
            cp16(sb + (uint32_t)i * 16, Kg + i * 4);
            cp16(sb + 24576u + (uint32_t)i * 16, Vg + i * 4);
            cp16(sb + 49152u + (uint32_t)((i >> 3) * 144 + (i & 7) * 16), Qg + i * 4);
        }
        CPC();
    }
    int it_i = 0;
#pragma unroll 1
    for (int t = t0; t < T_TOK; t += GRID2, ++it_i) {
        const int s = it_i & 1;
        CPW(0);
        __syncthreads();            // stage s staged; prev compute fully done
        const int tn = t + GRID2;
        if (tn < T_TOK) {           // prefetch next token -> stage s^1
            const float* Kg = g_K + (size_t)tn * JD;
            const float* Vg = g_V + (size_t)tn * JD;
            const float* Qg = g_Q + (size_t)tn * JD;
            uint32_t db = sb + (uint32_t)(s ^ 1) * (ST_F * 4);
#pragma unroll
            for (int it = 0; it < 6; ++it) {
                int i = tid + 256 * it;
                cp16(db + (uint32_t)i * 16, Kg + i * 4);
                cp16(db + 24576u + (uint32_t)i * 16, Vg + i * 4);
                cp16(db + 49152u + (uint32_t)((i >> 3) * 144 + (i & 7) * 16), Qg + i * 4);
            }
        }
        CPC();

        const float* stg = sm2 + s * ST_F;

        // ---- Phase C: scores + softmax (warp=head, lane=joint) ----
        if (lane < NJ) {
            const float* qp = stg + 12288 + warp * 864 + lane * 36;
            float q[32];
#pragma unroll
            for (int f4 = 0; f4 < 8; ++f4) {
                float4 v = *(const float4*)&qp[f4 * 4];
                q[4*f4+0] = v.x * SC; q[4*f4+1] = v.y * SC;
                q[4*f4+2] = v.z * SC; q[4*f4+3] = v.w * SC;
            }
            const float* kp = stg + warp * OUTJ;
            float sc[NJ];
#pragma unroll
            for (int m = 0; m < NJ; ++m) {
                const float4* kr = (const float4*)(kp + m * 32);
                float sv = 0.f;
#pragma unroll
                for (int f4 = 0; f4 < 8; ++f4) {
                    float4 kv = kr[f4];
                    sv += q[4*f4+0]*kv.x + q[4*f4+1]*kv.y + q[4*f4+2]*kv.z + q[4*f4+3]*kv.w;
                }
                sc[m] = sv;
            }
            float mx = sc[0];
#pragma unroll
            for (int m = 1; m < NJ; ++m) mx = fmaxf(mx, sc[m]);
            float sum = 0.f;
#pragma unroll
            for (int m = 0; m < NJ; ++m) { sc[m] = __expf(sc[m] - mx); sum += sc[m]; }
            const float inv = 1.f / sum;
            float* ap = att + warp * 672 + lane * 28;
#pragma unroll
            for (int mq = 0; mq < 6; ++mq)
                *(float4*)&ap[mq * 4] = make_float4(sc[4*mq]*inv, sc[4*mq+1]*inv,
                                                   sc[4*mq+2]*inv, sc[4*mq+3]*inv);
        }
        __syncthreads();

        // ---- Phase E: AV + residual (thread = channel (h,f)) ----
        float out[NJ];
        {
            const float* xg = x + (size_t)t * JD + tid;
#pragma unroll
            for (int n = 0; n < NJ; ++n) out[n] = xg[n * 256];
        }
        {
            const float* vp = stg + 6144 + warp * OUTJ + lane;
            const float* ap = att + warp * 672;
#pragma unroll
            for (int mq = 0; mq < 6; ++mq) {
                float v0 = vp[(4*mq+0) * 32];
                float v1 = vp[(4*mq+1) * 32];
                float v2 = vp[(4*mq+2) * 32];
                float v3 = vp[(4*mq+3) * 32];
#pragma unroll
                for (int n = 0; n < NJ; ++n) {
                    float4 a = *(const float4*)&ap[n * 28 + mq * 4];
                    out[n] += a.x*v0 + a.y*v1 + a.z*v2 + a.w*v3;
                }
            }
        }
        // ---- LN over 6144 (all 256 threads hold 24 values each) ----
        float s1 = 0.f, s2 = 0.f;
#pragma unroll
        for (int n = 0; n < NJ; ++n) { s1 += out[n]; s2 += out[n] * out[n]; }
#pragma unroll
        for (int o = 16; o; o >>= 1) {
            s1 += __shfl_xor_sync(0xffffffffu, s1, o);
            s2 += __shfl_xor_sync(0xffffffffu, s2, o);
        }
        if (lane == 0) { red[warp] = s1; red[8 + warp] = s2; }
        __syncthreads();
        float S1 = 0.f, S2 = 0.f;
#pragma unroll
        for (int w = 0; w < 8; ++w) { S1 += red[w]; S2 += red[8 + w]; }
        const float mu = S1 * (1.0f / JD);
        const float var = S2 * (1.0f / JD) - mu * mu;
        const float rstd = rsqrtf(var + 1e-5f);
        {
            float* yt = y + (size_t)t * JD + tid;
#pragma unroll
            for (int n = 0; n < NJ; ++n)
                yt[n * 256] = (out[n] - mu) * rstd * gw[n] + bw[n];
        }
    }
}

// ---------------------------------------------------------------------------
extern "C" void kernel_launch(void* const* d_in, const int* in_sizes, int n_in,
                              void* d_out, int out_size) {
    const float* x     = (const float*)d_in[0];
    const float* Wq    = (const float*)d_in[1];
    const float* bq    = (const float*)d_in[2];
    const float* Wk    = (const float*)d_in[3];
    const float* bk    = (const float*)d_in[4];
    const float* Wv    = (const float*)d_in[5];
    const float* bv    = (const float*)d_in[6];
    const float* gamma = (const float*)d_in[7];
    const float* beta  = (const float*)d_in[8];
    float* y = (float*)d_out;

    cudaFuncSetAttribute(qkv_gemm2_kernel, cudaFuncAttributeMaxDynamicSharedMemorySize, SMEM1);
    cudaFuncSetAttribute(attn_ln4_kernel,  cudaFuncAttributeMaxDynamicSharedMemorySize, SMEM2);

    prep_w_kernel<<<4608, 256>>>(Wq, Wk, Wv);
    prep_b_kernel<<<72, 256>>>(bq, bk, bv);
    qkv_gemm2_kernel<<<NJ * 6, 256, SMEM1>>>(x);
    attn_ln4_kernel<<<GRID2, 256, SMEM2>>>(x, gamma, beta, y);
}

// round 7
// speedup vs baseline: 1.3123x; 1.0082x over previous
#include <cuda_runtime.h>
#include <cstdint>
#include <cstddef>

#define T_TOK 8192
#define NJ    24
#define NH    8
#define FD    32
#define JD    6144
#define OUTJ  768

__device__ float g_Q[(size_t)T_TOK * JD];   // [t][h][n][f]
__device__ float g_K[(size_t)T_TOK * JD];
__device__ float g_V[(size_t)T_TOK * JD];
__device__ float g_Wt[(size_t)NJ * OUTJ * 256];   // [n][j][d], tf32-rounded
__device__ float g_bias[NJ * OUTJ];

__device__ __forceinline__ uint32_t smem_u32(const void* p) {
    uint32_t a;
    asm("{ .reg .u64 t; cvta.to.shared.u64 t, %1; cvt.u32.u64 %0, t; }" : "=r"(a) : "l"(p));
    return a;
}
__device__ __forceinline__ unsigned f2tf32(float x) {
    unsigned u;
    asm("cvt.rna.tf32.f32 %0, %1;" : "=r"(u) : "f"(x));
    return u;
}
__device__ __forceinline__ void mma_tf32(float* d, const unsigned* a, unsigned b0, unsigned b1) {
    asm volatile(
        "mma.sync.aligned.m16n8k8.row.col.f32.tf32.tf32.f32 "
        "{%0,%1,%2,%3}, {%4,%5,%6,%7}, {%8,%9}, {%0,%1,%2,%3};\n"
        : "+f"(d[0]), "+f"(d[1]), "+f"(d[2]), "+f"(d[3])
        : "r"(a[0]), "r"(a[1]), "r"(a[2]), "r"(a[3]), "r"(b0), "r"(b1));
}
__device__ __forceinline__ void cp16(uint32_t d, const void* s) {
    asm volatile("cp.async.cg.shared.global [%0], [%1], 16;" :: "r"(d), "l"(s));
}
#define CPC()  asm volatile("cp.async.commit_group;" ::: "memory")
#define CPW(n) asm volatile("cp.async.wait_group %0;" :: "n"(n) : "memory")

// ------------------------------- prep ---------------------------------------
__global__ void prep_w_kernel(const float* __restrict__ Wq, const float* __restrict__ Wk,
                              const float* __restrict__ Wv) {
    const size_t total = (size_t)NJ * OUTJ * 256;
    for (size_t i = (size_t)blockIdx.x * blockDim.x + threadIdx.x; i < total;
         i += (size_t)gridDim.x * blockDim.x) {
        int d = (int)(i & 255);
        size_t nj = i >> 8;
        int j = (int)(nj % OUTJ), n = (int)(nj / OUTJ);
        int h = (j >> 5) & 7, f = j & 31;
        float v;
        if (j < 256)      v = Wq[(((size_t)h * NJ + n) * 256 + d) * FD + f];
        else if (j < 512) v = Wk[((size_t)h * 256 + d) * FD + f];
        else              v = Wv[((size_t)h * 256 + d) * FD + f];
        g_Wt[i] = __uint_as_float(f2tf32(v));
    }
}
__global__ void prep_b_kernel(const float* __restrict__ bq, const float* __restrict__ bk,
                              const float* __restrict__ bv) {
    int i = blockIdx.x * blockDim.x + threadIdx.x;
    if (i < NJ * OUTJ) {
        int n = i / OUTJ, j = i % OUTJ, h = (j >> 5) & 7, f = j & 31;
        float v;
        if (j < 256)      v = bq[(h * NJ + n) * FD + f];
        else if (j < 512) v = bk[h * FD + f];
        else              v = bv[h * FD + f];
        g_bias[i] = v;
    }
}

// ------------------ K1: tf32 mma QKV GEMM, crosswise-vector B ----------------
// 144 CTAs = 24 joints x 6 col-blocks(128). CTA tile 256x128, warps 4m x 2n.
// B resident, one-time permute: within each 32-k chunk, k stored at position
// p=(k&3)*8+((k>>2)&1)+((k>>3)&3)*2, granule swizzled ^(row&7) ->
// thread (g,tg) reads its 2 k-step pair as one conflict-free LDS.128.
#define OFF_B    0
#define OFF_A    131072
#define OFF_BIAS 229376
#define SMEM1    229888

__global__ void __launch_bounds__(256, 1)
qkv_gemm4_kernel(const float* __restrict__ x) {
    extern __shared__ char sm[];
    const uint32_t sb = smem_u32(sm);
    float* bias_s = (float*)(sm + OFF_BIAS);
    const int tid = threadIdx.x, warp = tid >> 5, lane = tid & 31;
    const int g = lane >> 2, tg = lane & 3;
    const int wm = warp >> 1, wn = warp & 1;
    const int nj = blockIdx.x / 6, jb = blockIdx.x % 6;

    // prologue: A chunk0 + chunk1 via cp.async
    {
        const float* xb = x + (size_t)nj * 256;
#pragma unroll
        for (int it = 0; it < 8; ++it) {
            int i = tid + 256 * it;
            int row = i >> 3, c4 = i & 7;
            cp16(sb + OFF_A + (uint32_t)(row * 128 + ((c4 ^ (row & 7)) << 4)),
                 xb + (size_t)row * JD + c4 * 4);
        }
        CPC();
        const float* xb1 = xb + 32;
#pragma unroll
        for (int it = 0; it < 8; ++it) {
            int i = tid + 256 * it;
            int row = i >> 3, c4 = i & 7;
            cp16(sb + OFF_A + 32768u + (uint32_t)(row * 128 + ((c4 ^ (row & 7)) << 4)),
                 xb1 + (size_t)row * JD + c4 * 4);
        }
        CPC();
    }
    // one-time B permute (resident panel, read 256x afterwards)
    {
        const float4* W4 = (const float4*)(g_Wt + (size_t)(nj * OUTJ + jb * 128) * 256);
        float* Bp = (float*)(sm + OFF_B);
#pragma unroll
        for (int it = 0; it < 32; ++it) {
            int i = tid + 256 * it;            // 8192 float4
            int row = i >> 6, c4 = i & 63;
            float4 v = W4[i];
            int kb = c4 >> 3, k0 = (c4 & 7) * 4;
            float* dst = Bp + row * 256 + kb * 32;
            float e[4] = {v.x, v.y, v.z, v.w};
#pragma unroll
            for (int q = 0; q < 4; ++q) {
                int k = k0 + q;
                int p = (k & 3) * 8 + ((k >> 2) & 1) + ((k >> 3) & 3) * 2;
                int gr = (p >> 2) ^ (row & 7);
                dst[gr * 4 + (p & 3)] = e[q];
            }
        }
        if (tid < 128) bias_s[tid] = g_bias[nj * OUTJ + jb * 128 + tid];
    }
    __syncthreads();

    float acc[4][8][4];
#pragma unroll
    for (int mt = 0; mt < 4; ++mt)
#pragma unroll
        for (int nt = 0; nt < 8; ++nt)
#pragma unroll
            for (int r = 0; r < 4; ++r) acc[mt][nt][r] = 0.f;

    uint32_t aRow[4], bRowOff[8];
#pragma unroll
    for (int mt = 0; mt < 4; ++mt)
        aRow[mt] = (uint32_t)((wm * 64 + mt * 16 + g) * 128 + tg * 4);
#pragma unroll
    for (int nt = 0; nt < 8; ++nt)
        bRowOff[nt] = (uint32_t)(wn * 64 + nt * 8 + g) << 10;
    const uint32_t gr0 = (uint32_t)(((2 * tg) ^ g) << 4);
    const uint32_t gr1 = (uint32_t)(((2 * tg + 1) ^ g) << 4);

#pragma unroll 1
    for (int c = 0; c < 256; ++c) {           // chunk = (mtile c>>3, kb c&7)
        CPW(1);
        __syncthreads();
        if (c + 2 < 256) {
            int cn = c + 2;
            const float* xb = x + (size_t)(cn >> 3) * 256 * JD + (size_t)nj * 256 + (cn & 7) * 32;
            uint32_t stb = sb + OFF_A + (uint32_t)(cn % 3) * 32768u;
#pragma unroll
            for (int it = 0; it < 8; ++it) {
                int i = tid + 256 * it;
                int row = i >> 3, c4 = i & 7;
                cp16(stb + (uint32_t)(row * 128 + ((c4 ^ (row & 7)) << 4)),
                     xb + (size_t)row * JD + c4 * 4);
            }
        }
        CPC();

        const char* A0 = sm + OFF_A + (c % 3) * 32768;
        const char* Bc = sm + OFF_B + (c & 7) * 128;
#pragma unroll
        for (int kp = 0; kp < 2; ++kp) {
            const uint32_t grk = kp ? gr1 : gr0;
            float4 bf[8];
#pragma unroll
            for (int nt = 0; nt < 8; ++nt)
                bf[nt] = *(const float4*)(Bc + bRowOff[nt] + grk);
#pragma unroll
            for (int q = 0; q < 2; ++q) {
                const int kk = 2 * kp + q;
                const uint32_t x0 = (uint32_t)(((2 * kk) ^ g) << 4);
                const uint32_t x1 = (uint32_t)(((2 * kk + 1) ^ g) << 4);
                unsigned a[4][4];
#pragma unroll
                for (int mt = 0; mt < 4; ++mt) {
                    a[mt][0] = *(const unsigned*)(A0 + aRow[mt] + x0);
                    a[mt][1] = *(const unsigned*)(A0 + aRow[mt] + 1024 + x0);
                    a[mt][2] = *(const unsigned*)(A0 + aRow[mt] + x1);
                    a[mt][3] = *(const unsigned*)(A0 + aRow[mt] + 1024 + x1);
                }
#pragma unroll
                for (int mt = 0; mt < 4; ++mt)
#pragma unroll
                    for (int nt = 0; nt < 8; ++nt)
                        mma_tf32(acc[mt][nt], a[mt],
                                 __float_as_uint(q ? bf[nt].z : bf[nt].x),
                                 __float_as_uint(q ? bf[nt].w : bf[nt].y));
            }
        }

        if ((c & 7) == 7) {                    // epilogue for this 256-row m-tile
            const int rbase = (c >> 3) * 256 + wm * 64 + g;
#pragma unroll
            for (int mt = 0; mt < 4; ++mt)
#pragma unroll
                for (int nt = 0; nt < 8; ++nt) {
                    int jl = wn * 64 + nt * 8 + tg * 2;
                    int jg = jb * 128 + jl;
                    float* outp = (jg < 256) ? g_Q : ((jg < 512) ? g_K : g_V);
                    int h = (jg >> 5) & 7, f = jg & 31;
                    float b0 = bias_s[jl], b1 = bias_s[jl + 1];
                    size_t o0 = (size_t)(rbase + mt * 16) * JD + h * OUTJ + nj * 32 + f;
                    *(float2*)&outp[o0] =
                        make_float2(acc[mt][nt][0] + b0, acc[mt][nt][1] + b1);
                    *(float2*)&outp[o0 + 8 * JD] =
                        make_float2(acc[mt][nt][2] + b0, acc[mt][nt][3] + b1);
                    acc[mt][nt][0] = acc[mt][nt][1] = acc[mt][nt][2] = acc[mt][nt][3] = 0.f;
                }
        }
    }
}

// -------- K2: 2-CTA/SM attention + residual + LN -----------------------------
// 296 persistent CTAs x 256 thr, <=128 regs, 95.5KB smem (single-buffer K/Q/V).
// Overlap: V(t) loads during phase C; KQ(t+1) loads during phase E.
#define GRID2   296
// byte offsets
#define O2_K    0u          // 24576 B (6144 f)
#define O2_Q    24576u      // 27648 B (192 rows x 36 f padded)
#define O2_V    52224u      // 24576 B
#define O2_ATT  76800u      // 8*24*24 f = 18432 B
#define O2_RED  95232u      // 256 B
#define SMEM2   95488

__global__ void __launch_bounds__(256, 2)
attn_ln5_kernel(const float* __restrict__ x, const float* __restrict__ gamma,
                const float* __restrict__ beta, float* __restrict__ y) {
    extern __shared__ float sm2[];
    float* att = sm2 + (O2_ATT / 4);
    float* red = sm2 + (O2_RED / 4);
    const uint32_t sb = smem_u32(sm2);
    const int tid = threadIdx.x, warp = tid >> 5, lane = tid & 31;
    const int t0 = blockIdx.x;
    const float SC = 0.17677669529663687f;   // 1/sqrt(32)

    // prologue: KQ(t0) group, then V(t0) group
    {
        const float* Kg = g_K + (size_t)t0 * JD;
        const float* Qg = g_Q + (size_t)t0 * JD;
#pragma unroll
        for (int it = 0; it < 6; ++it) {
            int i = tid + 256 * it;          // 1536 float4 each
            cp16(sb + O2_K + (uint32_t)i * 16, Kg + i * 4);
            cp16(sb + O2_Q + (uint32_t)((i >> 3) * 144 + (i & 7) * 16), Qg + i * 4);
        }
        CPC();
        const float* Vg = g_V + (size_t)t0 * JD;
#pragma unroll
        for (int it = 0; it < 6; ++it) {
            int i = tid + 256 * it;
            cp16(sb + O2_V + (uint32_t)i * 16, Vg + i * 4);
        }
        CPC();
    }

#pragma unroll 1
    for (int t = t0; t < T_TOK; t += GRID2) {
        CPW(1);                  // KQ(t) ready (V(t) may still be in flight)
        __syncthreads();

        // ---- Phase C: scores + softmax (warp=head, lane=joint) ----
        if (lane < NJ) {
            const float* qp = sm2 + (O2_Q / 4) + (warp * NJ + lane) * 36;
            float q[32];
#pragma unroll
            for (int f4 = 0; f4 < 8; ++f4) {
                float4 v = *(const float4*)&qp[f4 * 4];
                q[4*f4+0] = v.x * SC; q[4*f4+1] = v.y * SC;
                q[4*f4+2] = v.z * SC; q[4*f4+3] = v.w * SC;
            }
            const float* kp = sm2 + warp * OUTJ;
            float sc[NJ];
#pragma unroll
            for (int m = 0; m < NJ; ++m) {
                const float4* kr = (const float4*)(kp + m * 32);
                float sv = 0.f;
#pragma unroll
                for (int f4 = 0; f4 < 8; ++f4) {
                    float4 kv = kr[f4];
                    sv += q[4*f4+0]*kv.x + q[4*f4+1]*kv.y + q[4*f4+2]*kv.z + q[4*f4+3]*kv.w;
                }
                sc[m] = sv;
            }
            float mx = sc[0];
#pragma unroll
            for (int m = 1; m < NJ; ++m) mx = fmaxf(mx, sc[m]);
            float sum = 0.f;
#pragma unroll
            for (int m = 0; m < NJ; ++m) { sc[m] = __expf(sc[m] - mx); sum += sc[m]; }
            const float inv = 1.f / sum;
            float* ap = att + warp * 576 + lane * 24;
#pragma unroll
            for (int mq = 0; mq < 6; ++mq)
                *(float4*)&ap[mq * 4] = make_float4(sc[4*mq]*inv, sc[4*mq+1]*inv,
                                                   sc[4*mq+2]*inv, sc[4*mq+3]*inv);
        }
        __syncthreads();         // C done: att visible; K,Q free

        const int tn = t + GRID2;
        if (tn < T_TOK) {        // prefetch KQ(t+1) — overlaps phase E
            const float* Kg = g_K + (size_t)tn * JD;
            const float* Qg = g_Q + (size_t)tn * JD;
#pragma unroll
            for (int it = 0; it < 6; ++it) {
                int i = tid + 256 * it;
                cp16(sb + O2_K + (uint32_t)i * 16, Kg + i * 4);
                cp16(sb + O2_Q + (uint32_t)((i >> 3) * 144 + (i & 7) * 16), Qg + i * 4);
            }
        }
        CPC();
        CPW(1);                  // V(t) ready
        __syncthreads();

        // ---- Phase E: AV + residual (thread = channel (h,f)) ----
        float out[NJ];
        {
            const float* xg = x + (size_t)t * JD + tid;
#pragma unroll
            for (int n = 0; n < NJ; ++n) out[n] = xg[n * 256];
        }
        {
            const float* vp = sm2 + (O2_V / 4) + warp * OUTJ + lane;
            const float* ap = att + warp * 576;
#pragma unroll
            for (int mq = 0; mq < 6; ++mq) {
                float v0 = vp[(4*mq+0) * 32];
                float v1 = vp[(4*mq+1) * 32];
                float v2 = vp[(4*mq+2) * 32];
                float v3 = vp[(4*mq+3) * 32];
#pragma unroll
                for (int n = 0; n < NJ; ++n) {
                    float4 a = *(const float4*)&ap[n * 24 + mq * 4];
                    out[n] += a.x*v0 + a.y*v1 + a.z*v2 + a.w*v3;
                }
            }
        }
        // ---- LN over 6144 ----
        float s1 = 0.f, s2 = 0.f;
#pragma unroll
        for (int n = 0; n < NJ; ++n) { s1 += out[n]; s2 += out[n] * out[n]; }
#pragma unroll
        for (int o = 16; o; o >>= 1) {
            s1 += __shfl_xor_sync(0xffffffffu, s1, o);
            s2 += __shfl_xor_sync(0xffffffffu, s2, o);
        }
        if (lane == 0) { red[warp] = s1; red[8 + warp] = s2; }
        __syncthreads();         // V reads + red writes complete

        if (tn < T_TOK) {        // prefetch V(t+1) — overlaps epilogue
            const float* Vg = g_V + (size_t)tn * JD;
#pragma unroll
            for (int it = 0; it < 6; ++it) {
                int i = tid + 256 * it;
                cp16(sb + O2_V + (uint32_t)i * 16, Vg + i * 4);
            }
        }
        CPC();

        float S1 = 0.f, S2 = 0.f;
#pragma unroll
        for (int w = 0; w < 8; ++w) { S1 += red[w]; S2 += red[8 + w]; }
        const float mu = S1 * (1.0f / JD);
        const float var = S2 * (1.0f / JD) - mu * mu;
        const float rstd = rsqrtf(var + 1e-5f);
        {
            float* yt = y + (size_t)t * JD + tid;
            const float* gp = gamma + tid;
            const float* bp = beta + tid;
#pragma unroll
            for (int n = 0; n < NJ; ++n)
                yt[n * 256] = (out[n] - mu) * rstd * gp[n * 256] + bp[n * 256];
        }
    }
}

// ---------------------------------------------------------------------------
extern "C" void kernel_launch(void* const* d_in, const int* in_sizes, int n_in,
                              void* d_out, int out_size) {
    const float* x     = (const float*)d_in[0];
    const float* Wq    = (const float*)d_in[1];
    const float* bq    = (const float*)d_in[2];
    const float* Wk    = (const float*)d_in[3];
    const float* bk    = (const float*)d_in[4];
    const float* Wv    = (const float*)d_in[5];
    const float* bv    = (const float*)d_in[6];
    const float* gamma = (const float*)d_in[7];
    const float* beta  = (const float*)d_in[8];
    float* y = (float*)d_out;

    cudaFuncSetAttribute(qkv_gemm4_kernel, cudaFuncAttributeMaxDynamicSharedMemorySize, SMEM1);
    cudaFuncSetAttribute(attn_ln5_kernel,  cudaFuncAttributeMaxDynamicSharedMemorySize, SMEM2);

    prep_w_kernel<<<4608, 256>>>(Wq, Wk, Wv);
    prep_b_kernel<<<72, 256>>>(bq, bk, bv);
    qkv_gemm4_kernel<<<NJ * 6, 256, SMEM1>>>(x);
    attn_ln5_kernel<<<GRID2, 256, SMEM2>>>(x, gamma, beta, y);
}